// round 3
// baseline (speedup 1.0000x reference)
#include <cuda_runtime.h>

// Problem dims
#define HH 160
#define WW 160
#define DD 96
#define NB 2
#define NC 4
#define BC 8
#define HO 154
#define WO 154
#define DO2 90
#define WIN 7

// Tiling
#define TW 12
#define TWF (TW+6)       // 18 input w footprint
#define TH 22
#define THF (TH+6)       // 28 input planes
#define NWT 13           // ceil(154/12)
#define NHT 7            // 154 = 7*22
#define NTHREADS 512

#define NVOX_Y (NB*HH*WW*DD)            // 4,915,200
#define N_OUT  (BC*HO*WO*DO2)           // 17,074,080

#define COV_NORM 1.0208333333333333f    // 49/48
#define CCONST   4.5e-4f                // (0.03)^2/2
#define INV343   (1.0f/343.0f)

// smem layout (floats)
#define G_SZ    (3*TWF*DD)       // 5184
#define C_SZ    (3*TW*DD)        // 3456
#define SA_SZ   (3*TW*DO2)       // 3240
#define RING_SZ (7*3*TW*DO2)     // 22680
#define SMEM_FLOATS (G_SZ + C_SZ + SA_SZ + RING_SZ)   // 34560
#define SMEM_BYTES  (SMEM_FLOATS*4)                   // 138240

__device__ unsigned char gYm[NVOX_Y];
__device__ double g_acc;

__global__ void k_zero() { g_acc = 0.0; }

// y int32 -> uint8 (reference asks int64 but JAX x64-off materializes int32)
__global__ void k_conv(const int* __restrict__ y) {
    int i = blockIdx.x * blockDim.x + threadIdx.x;
    if (i < NVOX_Y) gYm[i] = (unsigned char)y[i];
}

__inline__ __device__ float warpReduceSum(float v) {
    #pragma unroll
    for (int o = 16; o > 0; o >>= 1) v += __shfl_down_sync(0xffffffffu, v, o);
    return v;
}

__global__ __launch_bounds__(NTHREADS)
void k_fused(const float* __restrict__ x) {
    extern __shared__ float sm[];
    float* G    = sm;             // [3][TWF][DD]
    float* Cb   = G + G_SZ;       // [3][TW][DD]   (W-window sums)
    float* Sa   = Cb + C_SZ;      // [3][TW][DO2]  (running H sum)
    float* Ring = Sa + SA_SZ;     // [7][3][TW][DO2]

    const int tid = threadIdx.x;
    const int wt  = blockIdx.x;
    const int ht  = blockIdx.y;
    const int bc  = blockIdx.z;
    const int b   = bc >> 2;
    const int c   = bc & 3;
    const int w0  = wt * TW;
    const int h0  = ht * TH;

    // zero Sacc + ring (contiguous)
    for (int i = tid; i < SA_SZ + RING_SZ; i += NTHREADS) Sa[i] = 0.f;
    __syncthreads();

    float local = 0.f;

    for (int ip = 0; ip < THF; ip++) {
        const int h = h0 + ip;

        // ---- stage A: compute fields g1,g2,g3 on footprint ----
        for (int ti = tid; ti < TWF * DD; ti += NTHREADS) {
            int w = ti / DD, d = ti - w * DD;
            int wg = w0 + w;
            float g1 = 0.f, g2 = 0.f, g3 = 0.f;
            if (wg < WW) {
                float xv = x[((bc * HH + h) * WW + wg) * DD + d];
                unsigned char yv = gYm[((b * HH + h) * WW + wg) * DD + d];
                if (yv == (unsigned char)c) {
                    float s = __fdividef(1.f, 1.f + __expf(-xv));
                    g1 = 1.f; g2 = s; g3 = s * s;
                }
            }
            G[(0 * TWF + w) * DD + d] = g1;
            G[(1 * TWF + w) * DD + d] = g2;
            G[(2 * TWF + w) * DD + d] = g3;
        }
        __syncthreads();

        // ---- stage B: 7-window along W (18 -> 12), sliding per (f, d, half) ----
        for (int ti = tid; ti < 3 * DD * 2; ti += NTHREADS) {
            int f    = ti / (DD * 2);
            int r    = ti - f * (DD * 2);
            int d    = r % DD;          // consecutive tid -> consecutive d: conflict-free
            int half = r / DD;
            int ws   = half * (TW / 2); // 0 or 6
            const float* gp = &G[(f * TWF) * DD + d];
            float s = 0.f;
            #pragma unroll
            for (int j = 0; j < WIN; j++) s += gp[(ws + j) * DD];
            Cb[(f * TW + ws) * DD + d] = s;
            #pragma unroll
            for (int k = 1; k < TW / 2; k++) {
                s += gp[(ws + k + 6) * DD] - gp[(ws + k - 1) * DD];
                Cb[(f * TW + ws + k) * DD + d] = s;
            }
        }
        __syncthreads();

        // ---- stage C: 7-window along D (96 -> 90) + ring + running H sum ----
        const int slot = ip % 7;
        for (int ti = tid; ti < 3 * TW * 10; ti += NTHREADS) {
            int f   = ti / (TW * 10);
            int r   = ti - f * (TW * 10);
            int wq  = r / 10;
            int seg = r - wq * 10;
            int d0  = seg * 9;          // 10 segments of 9 outputs: 90
            const float* cp = &Cb[(f * TW + wq) * DD + d0];
            float v[15];
            #pragma unroll
            for (int j = 0; j < 15; j++) v[j] = cp[j];
            float s = v[0] + v[1] + v[2] + v[3] + v[4] + v[5] + v[6];
            float* rp = &Ring[((slot * 3 + f) * TW + wq) * DO2 + d0];
            float* sp = &Sa[(f * TW + wq) * DO2 + d0];
            #pragma unroll
            for (int k = 0; k < 9; k++) {
                if (k) s += v[k + 6] - v[k - 1];
                float old = rp[k];      // plane ip-7 (or 0 for ip<7)
                rp[k] = s;
                sp[k] += s - old;
            }
        }
        __syncthreads();

        // ---- stage D: emit s_value for output plane h-6 ----
        if (ip >= 6) {
            for (int ti = tid; ti < TW * DO2; ti += NTHREADS) {
                int wq = ti / DO2, d = ti - wq * DO2;
                if (w0 + wq < WO) {
                    float s1 = Sa[(0 * TW + wq) * DO2 + d];   // Sum(m)
                    float s2 = Sa[(1 * TW + wq) * DO2 + d];   // Sum(m*s)
                    float s3 = Sa[(2 * TW + wq) * DO2 + d];   // Sum(m*s^2)
                    float Sx  = s2 + 0.5f  * (343.f - s1);
                    float Sxx = s3 + 0.25f * (343.f - s1);
                    float ux = Sx * INV343, uy = s1 * INV343;
                    float vx  = COV_NORM * (Sxx * INV343 - ux * ux);
                    float vy  = COV_NORM * (s1  * INV343 - uy * uy);
                    float vxy = COV_NORM * (s2  * INV343 - ux * uy);
                    local += __fdividef(vxy + CCONST, vx * vy + CCONST);
                }
            }
        }
        // no trailing sync needed: next stage-A writes G only; the A->B sync
        // guarantees stage D (Sa reads) completed before stage C rewrites Sa.
    }

    // block reduction -> one atomicAdd per block
    __shared__ float red[NTHREADS / 32];
    float v = warpReduceSum(local);
    if ((tid & 31) == 0) red[tid >> 5] = v;
    __syncthreads();
    if (tid < 32) {
        v = (tid < NTHREADS / 32) ? red[tid] : 0.f;
        v = warpReduceSum(v);
        if (tid == 0) atomicAdd(&g_acc, (double)v);
    }
}

__global__ void k_final(float* out) {
    out[0] = 1.0f - (float)(g_acc * (1.0 / (double)N_OUT));
}

extern "C" void kernel_launch(void* const* d_in, const int* in_sizes, int n_in,
                              void* d_out, int out_size) {
    const float* x = (const float*)d_in[0];
    const int* y = (const int*)d_in[1];
    float* out = (float*)d_out;

    cudaFuncSetAttribute(k_fused, cudaFuncAttributeMaxDynamicSharedMemorySize, SMEM_BYTES);

    k_zero<<<1, 1>>>();
    k_conv<<<(NVOX_Y + 255) / 256, 256>>>(y);
    dim3 grid(NWT, NHT, BC);
    k_fused<<<grid, NTHREADS, SMEM_BYTES>>>(x);
    k_final<<<1, 1>>>(out);
}

// round 5
// speedup vs baseline: 1.0787x; 1.0787x over previous
#include <cuda_runtime.h>
#include <cuda_fp16.h>

#define HH 160
#define WW 160
#define DD 96
#define NB 2
#define NC 4
#define BC 8
#define HO 154
#define WO 154
#define DO2 90
#define WIN 7
#define HWP (HH*WW)              // 25600
#define CH_STRIDE (HH*WW*DD)     // 2457600
#define NVOX_Y (NB*HH*WW*DD)     // 4,915,200
#define N_OUT  (BC*HO*WO*DO2)    // 17,074,080
#define A_FIELD (BC*HWP*DO2)     // 18,432,000

#define COV_NORM 1.0208333333333333f
#define CCONST   4.5e-4f
#define INV343   (1.0f/343.0f)

// Static scratch
__device__ __half        gSv[NVOX_Y];       // sigmoid(x[b, y]) per voxel
__device__ unsigned char gY8[NVOX_Y];
__device__ __half        gAh[3*A_FIELD];    // [f][bc][hw][d'] D-windowed fields, fp16
__device__ double        g_acc;

__global__ void k_zero() { g_acc = 0.0; }

// ---- pre: per-voxel sigmoid of the selected channel (only 4.9M sigmoids) ----
__global__ void k_pre(const float* __restrict__ x, const int* __restrict__ y) {
    int i = blockIdx.x * blockDim.x + threadIdx.x;
    if (i >= NVOX_Y) return;
    int b = i / CH_STRIDE;
    int rem = i - b * CH_STRIDE;
    const float* xb = x + b * 4 * CH_STRIDE + rem;
    int yv = y[i];                       // int32 on device (JAX x64 off)
    float x0 = xb[0];
    float x1 = xb[CH_STRIDE];
    float x2 = xb[2 * CH_STRIDE];
    float x3 = xb[3 * CH_STRIDE];
    float xv = (yv == 0) ? x0 : (yv == 1) ? x1 : (yv == 2) ? x2 : x3;
    float s = __fdividef(1.f, 1.f + __expf(-xv));
    gSv[i] = __float2half(s);
    gY8[i] = (unsigned char)yv;
}

// ---- pass1: D-window (96->90) for all 4 channels from one read of sv/y ----
__global__ __launch_bounds__(384) void k_p1() {
    __shared__ float svs[4][DD];
    __shared__ int   ys[4][DD];
    int d  = threadIdx.x;                // 0..95
    int ly = threadIdx.y;                // 0..3
    int lg = blockIdx.x * 4 + ly;        // line over b*h*w = 51200
    int b  = lg / HWP;
    int hw = lg - b * HWP;
    svs[ly][d] = __half2float(gSv[lg * DD + d]);
    ys[ly][d]  = gY8[lg * DD + d];
    __syncthreads();
    if (d < DO2) {
        float a1[4] = {0,0,0,0}, a2[4] = {0,0,0,0}, a3[4] = {0,0,0,0};
        #pragma unroll
        for (int j = 0; j < WIN; j++) {
            int   yv = ys[ly][d + j];
            float sv = svs[ly][d + j];
            float sv2 = sv * sv;
            #pragma unroll
            for (int c = 0; c < 4; c++) {
                if (yv == c) { a1[c] += 1.f; a2[c] += sv; a3[c] += sv2; }
            }
        }
        #pragma unroll
        for (int c = 0; c < 4; c++) {
            int base = ((b * 4 + c) * HWP + hw) * DO2 + d;
            gAh[0 * A_FIELD + base] = __float2half(a1[c]);
            gAh[1 * A_FIELD + base] = __float2half(a2[c]);
            gAh[2 * A_FIELD + base] = __float2half(a3[c]);
        }
    }
}

__inline__ __device__ float warpReduceSum(float v) {
    #pragma unroll
    for (int o = 16; o > 0; o >>= 1) v += __shfl_down_sync(0xffffffffu, v, o);
    return v;
}

// ---- pass2+3 fused: W-window via smem tile, H-window via register ring ----
#define TWP 8
#define TWF2 (TWP + 6)               // 14
#define NWT2 20                      // 160/8 tiles (last partially used)
#define LOAD_ITEMS (3 * TWF2 * 45)   // 1890

__global__ __launch_bounds__(384) void k_p23() {
    __shared__ __half Gs[LOAD_ITEMS];
    __shared__ float red[12];
    int tid = threadIdx.x;
    int wt = blockIdx.x;
    int dh = blockIdx.y & 1;
    int hh = blockIdx.y >> 1;
    int bc = blockIdx.z;
    int w0 = wt * TWP;
    int d0 = dh * 45;
    int hstart = hh ? 77 : 0;
    int hend   = hh ? 160 : 83;

    int ty = tid / 45;               // w' within tile (0..7 for active)
    int tx = tid - ty * 45;          // d' within half
    bool active = tid < 360;
    bool wvalid = active && (w0 + ty < WO);

    float r1[7], r2[7], r3[7];
    #pragma unroll
    for (int j = 0; j < 7; j++) { r1[j] = 0.f; r2[j] = 0.f; r3[j] = 0.f; }
    float s1 = 0.f, s2 = 0.f, s3 = 0.f;
    float local = 0.f;

    for (int hb = hstart; hb < hend; hb += 7) {
        #pragma unroll
        for (int j = 0; j < 7; j++) {
            int h = hb + j;
            if (h < hend) {
                // load plane tile (3 fields x 14 w x 45 d) into smem
                for (int ti = tid; ti < LOAD_ITEMS; ti += 384) {
                    int f = ti / (TWF2 * 45);
                    int r = ti - f * (TWF2 * 45);
                    int i = r / 45;
                    int dd = r - i * 45;
                    int wg = w0 + i; if (wg > WW - 1) wg = WW - 1;  // clamped reads feed only discarded outputs
                    Gs[ti] = gAh[((f * BC + bc) * HWP + h * WW + wg) * DO2 + d0 + dd];
                }
                __syncthreads();
                if (active) {
                    float w1 = 0.f, w2 = 0.f, w3 = 0.f;
                    #pragma unroll
                    for (int k = 0; k < WIN; k++) {
                        int o = (ty + k) * 45 + tx;
                        w1 += __half2float(Gs[0 * (TWF2 * 45) + o]);
                        w2 += __half2float(Gs[1 * (TWF2 * 45) + o]);
                        w3 += __half2float(Gs[2 * (TWF2 * 45) + o]);
                    }
                    // H-window running sum with 7-deep register ring (slot = j)
                    s1 += w1 - r1[j]; r1[j] = w1;
                    s2 += w2 - r2[j]; r2[j] = w2;
                    s3 += w3 - r3[j]; r3[j] = w3;
                    if (wvalid && h >= hstart + 6) {
                        float Sx  = s2 + 0.5f  * (343.f - s1);
                        float Sxx = s3 + 0.25f * (343.f - s1);
                        float ux = Sx * INV343, uy = s1 * INV343;
                        float vx  = COV_NORM * (Sxx * INV343 - ux * ux);
                        float vy  = COV_NORM * (s1  * INV343 - uy * uy);
                        float vxy = COV_NORM * (s2  * INV343 - ux * uy);
                        local += __fdividef(vxy + CCONST, vx * vy + CCONST);
                    }
                }
                __syncthreads();
            }
        }
    }

    float v = warpReduceSum(local);
    if ((tid & 31) == 0) red[tid >> 5] = v;
    __syncthreads();
    if (tid < 32) {
        v = (tid < 12) ? red[tid] : 0.f;
        v = warpReduceSum(v);
        if (tid == 0) atomicAdd(&g_acc, (double)v);
    }
}

__global__ void k_final(float* out) {
    out[0] = 1.0f - (float)(g_acc * (1.0 / (double)N_OUT));
}

extern "C" void kernel_launch(void* const* d_in, const int* in_sizes, int n_in,
                              void* d_out, int out_size) {
    const float* x = (const float*)d_in[0];
    const int* y = (const int*)d_in[1];
    float* out = (float*)d_out;

    k_zero<<<1, 1>>>();
    k_pre<<<(NVOX_Y + 255) / 256, 256>>>(x, y);
    {
        dim3 blk(96, 4);
        k_p1<<<(NB * HWP) / 4, blk>>>();     // 12800 blocks
    }
    {
        dim3 grid(NWT2, 4, BC);              // 20 x (2 dhalf * 2 hhalf) x 8 = 640 blocks
        k_p23<<<grid, 384>>>();
    }
    k_final<<<1, 1>>>(out);
}

// round 8
// speedup vs baseline: 1.8617x; 1.7258x over previous
#include <cuda_runtime.h>
#include <cuda_fp16.h>

#define HH 160
#define WW 160
#define DD 96
#define NB 2
#define NC 4
#define BC 8
#define HO 154
#define WO 154
#define DO2 90
#define WIN 7
#define HWP (HH*WW)
#define CH_STRIDE (HH*WW*DD)
#define NVOX_Y (NB*HH*WW*DD)
#define N_OUT  (BC*HO*WO*DO2)
#define A_FIELD (BC*HWP*DO2)         // 18,432,000
#define B_LINE  (WO*DO2)             // 13860
#define B_FIELD (BC*HH*B_LINE)       // 17,740,800

#define COV_NORM 1.0208333333333333f
#define CCONST   4.5e-4f
#define INV343   (1.0f/343.0f)

__device__ __half gAh[3*A_FIELD];    // [f][bc][h][w][d'] fp16
__device__ __half gBh[3*B_FIELD];    // [f][bc][h][w'][d'] fp16
__device__ double g_acc;

__global__ void k_zero() { g_acc = 0.0; }

// ---- pass1: sigmoid of selected channel + D-window for all 4 channels ----
// block (96,4): 4 (b,h,w)-lines; thread.x = d
__global__ __launch_bounds__(384) void k_p1(const float* __restrict__ x,
                                            const int* __restrict__ y) {
    __shared__ float svs[4][DD];
    __shared__ int   ys[4][DD];
    int d  = threadIdx.x;
    int ly = threadIdx.y;
    int lg = blockIdx.x * 4 + ly;        // line over NB*HWP = 51200
    int b  = lg / HWP;
    int hw = lg - b * HWP;
    int yv = y[lg * DD + d];             // int32 (JAX x64 off)
    const float* xb = x + (b * 4 * HWP + hw) * DD + d;
    float x0 = xb[0];
    float x1 = xb[CH_STRIDE];
    float x2 = xb[2 * CH_STRIDE];
    float x3 = xb[3 * CH_STRIDE];
    float xv = (yv == 0) ? x0 : (yv == 1) ? x1 : (yv == 2) ? x2 : x3;
    svs[ly][d] = __fdividef(1.f, 1.f + __expf(-xv));
    ys[ly][d]  = yv;
    __syncthreads();
    if (d < DO2) {
        float a1[4] = {0,0,0,0}, a2[4] = {0,0,0,0}, a3[4] = {0,0,0,0};
        #pragma unroll
        for (int j = 0; j < WIN; j++) {
            int   yw  = ys[ly][d + j];
            float sv  = svs[ly][d + j];
            float sv2 = sv * sv;
            #pragma unroll
            for (int c = 0; c < 4; c++)
                if (yw == c) { a1[c] += 1.f; a2[c] += sv; a3[c] += sv2; }
        }
        #pragma unroll
        for (int c = 0; c < 4; c++) {
            int base = ((b * 4 + c) * HWP + hw) * DO2 + d;
            gAh[0 * A_FIELD + base] = __float2half(a1[c]);
            gAh[1 * A_FIELD + base] = __float2half(a2[c]);
            gAh[2 * A_FIELD + base] = __float2half(a3[c]);
        }
    }
}

// ---- pass2: W-window, sliding sum, 4 w-chunks x 96 d-threads per (bc,h) ----
__global__ __launch_bounds__(384) void k_p2() {
    int tid   = threadIdx.x;
    int chunk = tid / 96;                // 0..3
    int dl    = tid - chunk * 96;        // 0..95
    if (dl >= DO2) return;
    int h  = blockIdx.x % HH;
    int bc = blockIdx.x / HH;
    int c0 = chunk * 40;
    int wlimit = (c0 + 46 < WW) ? c0 + 46 : WW;

    const __half* A0 = gAh + ((0 * BC + bc) * HWP + h * WW) * DO2 + dl;
    const __half* A1 = gAh + ((1 * BC + bc) * HWP + h * WW) * DO2 + dl;
    const __half* A2 = gAh + ((2 * BC + bc) * HWP + h * WW) * DO2 + dl;
    __half* B0 = gBh + ((0 * BC + bc) * HH + h) * B_LINE + dl;
    __half* B1 = gBh + ((1 * BC + bc) * HH + h) * B_LINE + dl;
    __half* B2 = gBh + ((2 * BC + bc) * HH + h) * B_LINE + dl;

    float s1 = 0.f, s2 = 0.f, s3 = 0.f;
    for (int w = c0; w < wlimit; w++) {
        s1 += __half2float(A0[w * DO2]);
        s2 += __half2float(A1[w * DO2]);
        s3 += __half2float(A2[w * DO2]);
        if (w >= c0 + 7) {               // L1-hot re-read of w-7
            s1 -= __half2float(A0[(w - 7) * DO2]);
            s2 -= __half2float(A1[(w - 7) * DO2]);
            s3 -= __half2float(A2[(w - 7) * DO2]);
        }
        int wp = w - 6;
        if (wp >= c0 && wp < c0 + 40 && wp < WO) {
            B0[wp * DO2] = __float2half(s1);
            B1[wp * DO2] = __float2half(s2);
            B2[wp * DO2] = __float2half(s3);
        }
    }
}

__inline__ __device__ float warpReduceSum(float v) {
    #pragma unroll
    for (int o = 16; o > 0; o >>= 1) v += __shfl_down_sync(0xffffffffu, v, o);
    return v;
}

// ---- pass3: H-window via mod-7 register ring + s_value + reduction ----
__global__ __launch_bounds__(256) void k_p3() {
    int tid = threadIdx.x;
    int j   = blockIdx.x * 256 + tid;    // over WO*DO2 = 13860
    int hh  = blockIdx.y;                // 0/1 h-half
    int bc  = blockIdx.z;
    int hstart = hh ? 77 : 0;
    int hend   = hh ? 160 : 83;
    float local = 0.f;

    if (j < B_LINE) {
        const __half* P0 = gBh + (0 * BC + bc) * HH * B_LINE + j;
        const __half* P1 = gBh + (1 * BC + bc) * HH * B_LINE + j;
        const __half* P2 = gBh + (2 * BC + bc) * HH * B_LINE + j;
        float r1[7], r2[7], r3[7];
        #pragma unroll
        for (int k = 0; k < 7; k++) { r1[k] = 0.f; r2[k] = 0.f; r3[k] = 0.f; }
        float s1 = 0.f, s2 = 0.f, s3 = 0.f;

        for (int hb = hstart; hb < hend; hb += 7) {
            #pragma unroll
            for (int k = 0; k < 7; k++) {
                int h = hb + k;
                if (h < hend) {
                    float w1 = __half2float(P0[h * B_LINE]);
                    float w2 = __half2float(P1[h * B_LINE]);
                    float w3 = __half2float(P2[h * B_LINE]);
                    s1 += w1 - r1[k]; r1[k] = w1;
                    s2 += w2 - r2[k]; r2[k] = w2;
                    s3 += w3 - r3[k]; r3[k] = w3;
                    if (h >= hstart + 6) {
                        float Sx  = s2 + 0.5f  * (343.f - s1);
                        float Sxx = s3 + 0.25f * (343.f - s1);
                        float ux = Sx * INV343, uy = s1 * INV343;
                        float vx  = COV_NORM * (Sxx * INV343 - ux * ux);
                        float vy  = COV_NORM * (s1  * INV343 - uy * uy);
                        float vxy = COV_NORM * (s2  * INV343 - ux * uy);
                        local += __fdividef(vxy + CCONST, vx * vy + CCONST);
                    }
                }
            }
        }
    }

    __shared__ float red[8];
    float v = warpReduceSum(local);
    if ((tid & 31) == 0) red[tid >> 5] = v;
    __syncthreads();
    if (tid < 32) {
        v = (tid < 8) ? red[tid] : 0.f;
        v = warpReduceSum(v);
        if (tid == 0) atomicAdd(&g_acc, (double)v);
    }
}

__global__ void k_final(float* out) {
    out[0] = 1.0f - (float)(g_acc * (1.0 / (double)N_OUT));
}

extern "C" void kernel_launch(void* const* d_in, const int* in_sizes, int n_in,
                              void* d_out, int out_size) {
    const float* x = (const float*)d_in[0];
    const int* y = (const int*)d_in[1];
    float* out = (float*)d_out;

    k_zero<<<1, 1>>>();
    {
        dim3 blk(96, 4);
        k_p1<<<(NB * HWP) / 4, blk>>>(x, y);   // 12800 blocks
    }
    k_p2<<<BC * HH, 384>>>();                  // 1280 blocks
    {
        dim3 grid((B_LINE + 255) / 256, 2, BC); // 55 x 2 x 8 = 880 blocks
        k_p3<<<grid, 256>>>();
    }
    k_final<<<1, 1>>>(out);
}

// round 10
// speedup vs baseline: 2.3663x; 1.2711x over previous
#include <cuda_runtime.h>
#include <cuda_fp16.h>

#define HH 160
#define WW 160
#define DD 96
#define NB 2
#define NC 4
#define BC 8
#define HO 154
#define WO 154
#define DO2 90
#define WIN 7
#define HWP (HH*WW)
#define CH_STRIDE (HH*WW*DD)
#define N_OUT  (BC*HO*WO*DO2)
#define A_FIELD (BC*HWP*DO2)         // 18,432,000
#define B_LINE  (WO*DO2)             // 13860
#define B_FIELD (BC*HH*B_LINE)       // 17,740,800

#define COV_NORM 1.0208333333333333f
#define CCONST   4.5e-4f
#define INV343   (1.0f/343.0f)

__device__ __half gAh[3*A_FIELD];    // [f][bc][h][w][d'] fp16
__device__ __half gBh[3*B_FIELD];    // [f][bc][h][w'][d'] fp16
__device__ double g_acc;

// ---- pass1: sigmoid of selected channel + D-window for all 4 channels ----
__global__ __launch_bounds__(384) void k_p1(const float* __restrict__ x,
                                            const int* __restrict__ y) {
    __shared__ float svs[4][DD];
    __shared__ int   ys[4][DD];
    int d  = threadIdx.x;
    int ly = threadIdx.y;
    if (blockIdx.x == 0 && d == 0 && ly == 0) g_acc = 0.0;   // fold k_zero
    int lg = blockIdx.x * 4 + ly;        // line over NB*HWP = 51200
    int b  = lg / HWP;
    int hw = lg - b * HWP;
    int yv = y[lg * DD + d];             // int32 (JAX x64 off)
    const float* xb = x + (b * 4 * HWP + hw) * DD + d;
    float x0 = xb[0];
    float x1 = xb[CH_STRIDE];
    float x2 = xb[2 * CH_STRIDE];
    float x3 = xb[3 * CH_STRIDE];
    float xv = (yv == 0) ? x0 : (yv == 1) ? x1 : (yv == 2) ? x2 : x3;
    svs[ly][d] = __fdividef(1.f, 1.f + __expf(-xv));
    ys[ly][d]  = yv;
    __syncthreads();
    if (d < DO2) {
        float a1[4] = {0,0,0,0}, a2[4] = {0,0,0,0}, a3[4] = {0,0,0,0};
        #pragma unroll
        for (int j = 0; j < WIN; j++) {
            int   yw  = ys[ly][d + j];
            float sv  = svs[ly][d + j];
            float sv2 = sv * sv;
            #pragma unroll
            for (int c = 0; c < 4; c++)
                if (yw == c) { a1[c] += 1.f; a2[c] += sv; a3[c] += sv2; }
        }
        #pragma unroll
        for (int c = 0; c < 4; c++) {
            int base = ((b * 4 + c) * HWP + hw) * DO2 + d;
            gAh[0 * A_FIELD + base] = __float2half(a1[c]);
            gAh[1 * A_FIELD + base] = __float2half(a2[c]);
            gAh[2 * A_FIELD + base] = __float2half(a3[c]);
        }
    }
}

// ---- pass2: W-window, sliding sum, half2 width ----
// block: 192 threads = 4 w-chunks x 48 d-pairs (45 active); grid = BC*HH
__global__ __launch_bounds__(192) void k_p2() {
    int tid   = threadIdx.x;
    int chunk = tid / 48;
    int dp    = tid - chunk * 48;        // d-pair index, 0..44 active
    if (dp >= 45) return;
    int h  = blockIdx.x % HH;
    int bc = blockIdx.x / HH;
    int c0 = chunk * 40;
    int wlimit = (c0 + 46 < WW) ? c0 + 46 : WW;

    const __half2* A0 = (const __half2*)(gAh + ((0 * BC + bc) * HWP + h * WW) * DO2) + dp;
    const __half2* A1 = (const __half2*)(gAh + ((1 * BC + bc) * HWP + h * WW) * DO2) + dp;
    const __half2* A2 = (const __half2*)(gAh + ((2 * BC + bc) * HWP + h * WW) * DO2) + dp;
    __half2* B0 = (__half2*)(gBh + ((0 * BC + bc) * HH + h) * B_LINE) + dp;
    __half2* B1 = (__half2*)(gBh + ((1 * BC + bc) * HH + h) * B_LINE) + dp;
    __half2* B2 = (__half2*)(gBh + ((2 * BC + bc) * HH + h) * B_LINE) + dp;
    const int AS = DO2 / 2;              // half2 stride per w
    const int BS = DO2 / 2;

    float2 s1 = {0,0}, s2 = {0,0}, s3 = {0,0};
    for (int w = c0; w < wlimit; w++) {
        float2 v;
        v = __half22float2(A0[w * AS]); s1.x += v.x; s1.y += v.y;
        v = __half22float2(A1[w * AS]); s2.x += v.x; s2.y += v.y;
        v = __half22float2(A2[w * AS]); s3.x += v.x; s3.y += v.y;
        if (w >= c0 + 7) {               // L1-hot re-read of w-7
            v = __half22float2(A0[(w - 7) * AS]); s1.x -= v.x; s1.y -= v.y;
            v = __half22float2(A1[(w - 7) * AS]); s2.x -= v.x; s2.y -= v.y;
            v = __half22float2(A2[(w - 7) * AS]); s3.x -= v.x; s3.y -= v.y;
        }
        int wp = w - 6;
        if (wp >= c0 && wp < c0 + 40 && wp < WO) {
            B0[wp * BS] = __floats2half2_rn(s1.x, s1.y);
            B1[wp * BS] = __floats2half2_rn(s2.x, s2.y);
            B2[wp * BS] = __floats2half2_rn(s3.x, s3.y);
        }
    }
}

__inline__ __device__ float warpReduceSum(float v) {
    #pragma unroll
    for (int o = 16; o > 0; o >>= 1) v += __shfl_down_sync(0xffffffffu, v, o);
    return v;
}

__inline__ __device__ float svalue(float s1, float s2, float s3) {
    float Sx  = s2 + 0.5f  * (343.f - s1);
    float Sxx = s3 + 0.25f * (343.f - s1);
    float ux = Sx * INV343, uy = s1 * INV343;
    float vx  = COV_NORM * (Sxx * INV343 - ux * ux);
    float vy  = COV_NORM * (s1  * INV343 - uy * uy);
    float vxy = COV_NORM * (s2  * INV343 - ux * uy);
    return __fdividef(vxy + CCONST, vx * vy + CCONST);
}

// ---- pass3: H-window, half2 width, branch-free steady state, 3 h-segments ----
// seg output ranges: {0..51, 52..103, 104..153}; input planes [h0, h0+outs+6)
__global__ __launch_bounds__(256) void k_p3() {
    int tid = threadIdx.x;
    int j2  = blockIdx.x * 256 + tid;    // over B_LINE/2 = 6930
    int seg = blockIdx.y;
    int bc  = blockIdx.z;
    int h0   = seg * 52;
    int outs = (seg == 2) ? 50 : 52;
    int planes = outs + 6;               // 58, 58, 56
    float2 local = {0.f, 0.f};

    if (j2 < B_LINE / 2) {
        const __half2* P0 = (const __half2*)(gBh + (0 * BC + bc) * HH * B_LINE) + j2;
        const __half2* P1 = (const __half2*)(gBh + (1 * BC + bc) * HH * B_LINE) + j2;
        const __half2* P2 = (const __half2*)(gBh + (2 * BC + bc) * HH * B_LINE) + j2;
        const int HS = B_LINE / 2;       // half2 stride per h

        float2 r1[7], r2[7], r3[7];
        float2 s1 = {0,0}, s2 = {0,0}, s3 = {0,0};

        // group 0: fill 7 planes, emit once at k==6
        #pragma unroll
        for (int k = 0; k < 7; k++) {
            int h = h0 + k;
            float2 w1 = __half22float2(P0[h * HS]);
            float2 w2 = __half22float2(P1[h * HS]);
            float2 w3 = __half22float2(P2[h * HS]);
            s1.x += w1.x; s1.y += w1.y; r1[k] = w1;
            s2.x += w2.x; s2.y += w2.y; r2[k] = w2;
            s3.x += w3.x; s3.y += w3.y; r3[k] = w3;
        }
        local.x += svalue(s1.x, s2.x, s3.x);
        local.y += svalue(s1.y, s2.y, s3.y);

        int nfull = (planes - 7) / 7;
        int rem   = (planes - 7) % 7;
        int h = h0 + 7;
        for (int g = 0; g < nfull; g++, h += 7) {
            #pragma unroll
            for (int k = 0; k < 7; k++) {
                float2 w1 = __half22float2(P0[(h + k) * HS]);
                float2 w2 = __half22float2(P1[(h + k) * HS]);
                float2 w3 = __half22float2(P2[(h + k) * HS]);
                s1.x += w1.x - r1[k].x; s1.y += w1.y - r1[k].y; r1[k] = w1;
                s2.x += w2.x - r2[k].x; s2.y += w2.y - r2[k].y; r2[k] = w2;
                s3.x += w3.x - r3[k].x; s3.y += w3.y - r3[k].y; r3[k] = w3;
                local.x += svalue(s1.x, s2.x, s3.x);
                local.y += svalue(s1.y, s2.y, s3.y);
            }
        }
        #pragma unroll
        for (int k = 0; k < 6; k++) {
            if (k < rem) {
                float2 w1 = __half22float2(P0[(h + k) * HS]);
                float2 w2 = __half22float2(P1[(h + k) * HS]);
                float2 w3 = __half22float2(P2[(h + k) * HS]);
                s1.x += w1.x - r1[k].x; s1.y += w1.y - r1[k].y; r1[k] = w1;
                s2.x += w2.x - r2[k].x; s2.y += w2.y - r2[k].y; r2[k] = w2;
                s3.x += w3.x - r3[k].x; s3.y += w3.y - r3[k].y; r3[k] = w3;
                local.x += svalue(s1.x, s2.x, s3.x);
                local.y += svalue(s1.y, s2.y, s3.y);
            }
        }
    }

    __shared__ float red[8];
    float v = warpReduceSum(local.x + local.y);
    if ((tid & 31) == 0) red[tid >> 5] = v;
    __syncthreads();
    if (tid < 32) {
        v = (tid < 8) ? red[tid] : 0.f;
        v = warpReduceSum(v);
        if (tid == 0) atomicAdd(&g_acc, (double)v);
    }
}

__global__ void k_final(float* out) {
    out[0] = 1.0f - (float)(g_acc * (1.0 / (double)N_OUT));
}

extern "C" void kernel_launch(void* const* d_in, const int* in_sizes, int n_in,
                              void* d_out, int out_size) {
    const float* x = (const float*)d_in[0];
    const int* y = (const int*)d_in[1];
    float* out = (float*)d_out;

    {
        dim3 blk(96, 4);
        k_p1<<<(NB * HWP) / 4, blk>>>(x, y);     // 12800 blocks
    }
    k_p2<<<BC * HH, 192>>>();                    // 1280 blocks
    {
        dim3 grid((B_LINE / 2 + 255) / 256, 3, BC); // 28 x 3 x 8 = 672 blocks
        k_p3<<<grid, 256>>>();
    }
    k_final<<<1, 1>>>(out);
}